// round 9
// baseline (speedup 1.0000x reference)
#include <cuda_runtime.h>
#include <math.h>

#define BB 64
#define PP 24564
#define CC 81
#define TT 24
#define THRESH_F 0.5f
#define FULLMASK 0xffffffffu

#define CW_WARPS 4                    // warps per k_conf block
#define CW_ROWS 32                    // rows per warp (one row per lane)
#define CW_F4 ((CW_ROWS * CC) / 4)    // 648 float4 per warp tile

// ---------------------------------------------------------------------------
// Scratch (device globals — no allocation allowed)
// ---------------------------------------------------------------------------
__device__ unsigned long long g_bp[BB * TT];        // packed (iou_bits<<32)|~p
__device__ unsigned char g_lbl[(size_t)BB * PP];    // 0 = negative, else class label
__device__ unsigned char g_match[(size_t)BB * PP];  // 0xFF = bestov<=0.5, else bt
__device__ float g_closs[(size_t)BB * PP];          // per (b,p) neg conf loss
__device__ double g_loc, g_poscls, g_negcls;
__device__ int g_numpos[BB];
__device__ int g_nsel;

// ---------------------------------------------------------------------------
// Kernel 0: zero-init scratch
// ---------------------------------------------------------------------------
__global__ void k_init() {
    int i = blockIdx.x * blockDim.x + threadIdx.x;
    if (i < BB * TT) g_bp[i] = 0ULL;
    if (i < BB) g_numpos[i] = 0;
    if (i == 0) { g_loc = 0.0; g_poscls = 0.0; g_negcls = 0.0; g_nsel = 0; }
}

// ---------------------------------------------------------------------------
// Kernel 1 (merged): ONE IoU pass does both jobs.
//  - per-prior best truth (sequential register argmax, first-index ties)
//  - per-truth best prior (smem u64 atomicMax behind __any_sync early-out)
//  - best>0.5 rows: label + smooth-L1 loc loss + num_pos, g_match=bt
//  - best<=0.5 rows: g_match=0xFF (k_fix may flip them via scatter)
// ---------------------------------------------------------------------------
__global__ void __launch_bounds__(256) k_matchA(const float* __restrict__ loc_pred,
                                                const float* __restrict__ targets,
                                                const float* __restrict__ anchors) {
    __shared__ float4 s_box[TT];      // xyxy
    __shared__ float  s_ta[TT];       // truth area
    __shared__ float4 s_cwh[TT];      // cx,cy,w,h
    __shared__ float  s_lblv[TT];
    __shared__ unsigned long long s_best[TT];
    __shared__ double s_loc;
    __shared__ int s_np;

    const int b = blockIdx.y;
    const int tid = threadIdx.x;
    if (tid == 0) { s_loc = 0.0; s_np = 0; }
    if (tid < TT) {
        const float* tr = targets + ((size_t)b * TT + tid) * 5;
        float x0 = tr[0], y0 = tr[1], x1 = tr[2], y1 = tr[3];
        s_box[tid] = make_float4(x0, y0, x1, y1);
        s_ta[tid] = (x1 - x0) * (y1 - y0);
        s_cwh[tid] = make_float4((x0 + x1) * 0.5f, (y0 + y1) * 0.5f, x1 - x0, y1 - y0);
        s_lblv[tid] = tr[4];
        s_best[tid] = 0ULL;
    }
    __syncthreads();

    const int p = blockIdx.x * blockDim.x + tid;
    const bool valid = (p < PP);
    float4 a = make_float4(0.f, 0.f, 1.f, 1.f);
    if (valid) a = ((const float4*)anchors)[p];
    const float ax0 = a.x - a.z * 0.5f, ay0 = a.y - a.w * 0.5f;
    const float ax1 = a.x + a.z * 0.5f, ay1 = a.y + a.w * 0.5f;
    const float aarea = (ax1 - ax0) * (ay1 - ay0);

    float best = -1.0f; int bt = 0;
    #pragma unroll
    for (int t = 0; t < TT; t++) {
        float4 tb = s_box[t];
        float lx = fmaxf(tb.x, ax0), ly = fmaxf(tb.y, ay0);
        float rx = fminf(tb.z, ax1), ry = fminf(tb.w, ay1);
        float w = fmaxf(rx - lx, 0.f), h = fmaxf(ry - ly, 0.f);
        float inter = w * h;
        float iou = __fdividef(inter, s_ta[t] + aarea - inter);
        if (iou > best) { best = iou; bt = t; }       // strict >: first index wins

        unsigned long long pk = 0ULL;
        if (valid)
            pk = ((unsigned long long)__float_as_uint(iou) << 32)
                 | (unsigned long long)(unsigned int)(~p);
        // Early-out: s_best[t] monotonic; a stale read only skips the skip.
        unsigned long long cur = s_best[t];
        if (__any_sync(FULLMASK, pk > cur)) {
            #pragma unroll
            for (int o = 16; o; o >>= 1) {
                unsigned long long oth = __shfl_down_sync(FULLMASK, pk, o);
                if (oth > pk) pk = oth;
            }
            if ((tid & 31) == 0) atomicMax(&s_best[t], pk);
        }
    }

    if (valid) {
        const size_t row = (size_t)b * PP + p;
        unsigned char lbl = 0, mb = 0xFF;
        if (best > THRESH_F) {
            mb = (unsigned char)bt;
            lbl = (unsigned char)(int)s_lblv[bt];
            float4 lp = ((const float4*)loc_pred)[row];
            float4 c = s_cwh[bt];
            float e0 = (c.x - a.x) / a.z;
            float e1 = (c.y - a.y) / a.w;
            float e2 = __logf(c.z) - __logf(a.z);
            float e3 = __logf(c.w) - __logf(a.w);
            float d, ad, lt = 0.f;
            d = lp.x - e0; ad = fabsf(d); lt += (ad < 1.f) ? 0.5f * d * d : ad - 0.5f;
            d = lp.y - e1; ad = fabsf(d); lt += (ad < 1.f) ? 0.5f * d * d : ad - 0.5f;
            d = lp.z - e2; ad = fabsf(d); lt += (ad < 1.f) ? 0.5f * d * d : ad - 0.5f;
            d = lp.w - e3; ad = fabsf(d); lt += (ad < 1.f) ? 0.5f * d * d : ad - 0.5f;
            atomicAdd(&s_loc, (double)lt);
            atomicAdd(&s_np, 1);
        }
        g_lbl[row] = lbl;
        g_match[row] = mb;
    }
    __syncthreads();
    if (tid < TT) atomicMax(&g_bp[b * TT + tid], s_best[tid]);
    if (tid == 0 && s_np) {
        atomicAdd(&g_loc, s_loc);
        atomicAdd(&g_numpos[b], s_np);
    }
}

// ---------------------------------------------------------------------------
// Kernel 2: scatter fixup — 64 blocks x 32 threads, 1536 candidate rows.
// Row p = best_prior[b][t] becomes positive with truth t (last t wins among
// duplicates) iff its best overlap was <= 0.5 (g_match == 0xFF).
// ---------------------------------------------------------------------------
__global__ void k_fix(const float* __restrict__ loc_pred,
                      const float* __restrict__ targets,
                      const float* __restrict__ anchors) {
    const int b = blockIdx.x;
    const int t = threadIdx.x;
    if (t >= TT) return;
    unsigned long long pk = g_bp[b * TT + t];
    const int p = (int)(~(unsigned int)(pk & 0xFFFFFFFFull));
    unsigned int peers = __match_any_sync(0x00FFFFFFu, p);
    if (t != 31 - __clz(peers)) return;          // last t wins
    const size_t row = (size_t)b * PP + p;
    if (g_match[row] != 0xFF) return;            // bt-match already positive

    const float* tr = targets + ((size_t)b * TT + t) * 5;
    float x0 = tr[0], y0 = tr[1], x1 = tr[2], y1 = tr[3];
    g_lbl[row] = (unsigned char)(int)tr[4];

    float4 a = ((const float4*)anchors)[p];
    float4 lp = ((const float4*)loc_pred)[row];
    float e0 = ((x0 + x1) * 0.5f - a.x) / a.z;
    float e1 = ((y0 + y1) * 0.5f - a.y) / a.w;
    float e2 = __logf(x1 - x0) - __logf(a.z);
    float e3 = __logf(y1 - y0) - __logf(a.w);
    float d, ad, lt = 0.f;
    d = lp.x - e0; ad = fabsf(d); lt += (ad < 1.f) ? 0.5f * d * d : ad - 0.5f;
    d = lp.y - e1; ad = fabsf(d); lt += (ad < 1.f) ? 0.5f * d * d : ad - 0.5f;
    d = lp.z - e2; ad = fabsf(d); lt += (ad < 1.f) ? 0.5f * d * d : ad - 0.5f;
    d = lp.w - e3; ad = fabsf(d); lt += (ad < 1.f) ? 0.5f * d * d : ad - 0.5f;
    atomicAdd(&g_loc, (double)lt);
    atomicAdd(&g_numpos[b], 1);
}

// ---------------------------------------------------------------------------
// Kernel 3: the 509 MB streaming pass — warp-self-contained tiles.
// Each warp owns 32 rows (10.4 KB, 648 float4, base 16B-aligned): stages its
// own smem region (coalesced LDG.128 -> STS.128, unroll 4 for MLP), then
// __syncwarp (NO block barrier) and lane = row: 81 conflict-free scalar LDS
// (stride 81 -> bank 17*lane+e mod 32) + 81 __expf. Warps stall independently
// so resident warps keep DRAM and MUFU pipes fed continuously.
// ---------------------------------------------------------------------------
__global__ void __launch_bounds__(CW_WARPS * 32) k_conf(const float* __restrict__ conf_pred) {
    __shared__ float s[CW_WARPS][CW_ROWS * CC];      // 4 x 10368 B

    const int lane = threadIdx.x & 31;
    const int w = threadIdx.x >> 5;
    const size_t wg = (size_t)blockIdx.x * CW_WARPS + w;   // global warp id
    const size_t row0 = wg * CW_ROWS;

    // stage: 648 float4, warp-private region, no register blowup
    const float4* src = (const float4*)(conf_pred + row0 * CC);
    float4* dst = (float4*)s[w];
    #pragma unroll 4
    for (int i = lane; i < CW_F4; i += 32)
        dst[i] = __ldcs(src + i);
    __syncwarp();

    // one lane = one row
    const float* rp = s[w] + lane * CC;
    float a0 = 0.f, a1 = 0.f, a2 = 0.f;
    #pragma unroll 9
    for (int e = 0; e < CC; e += 3) {
        a0 += __expf(rp[e]);
        a1 += __expf(rp[e + 1]);
        a2 += __expf(rp[e + 2]);
    }
    const float lse = __logf((a0 + a1) + a2);

    const size_t row = row0 + lane;
    const int lbl = g_lbl[row];             // coalesced byte load
    float closs = 0.f;
    if (lbl == 0) {
        closs = lse - rp[0];                // candidate negative
    } else {                                // positive (rare)
        atomicAdd(&g_poscls, (double)(lse - rp[lbl]));
    }
    g_closs[row] = closs;                   // coalesced store
}

// ---------------------------------------------------------------------------
// Kernel 4: per-batch exact K-th-largest; register-cached values, warp-
// aggregated histogram atomics (closs clusters into few bins).
// ---------------------------------------------------------------------------
__global__ void __launch_bounds__(1024) k_select() {
    __shared__ int hist[256];
    __shared__ unsigned int s_sel;
    __shared__ int s_r;
    __shared__ double s_sum;
    __shared__ int s_cnt;

    const int b = blockIdx.x;
    const int tid = threadIdx.x;
    const int lane = tid & 31;
    const int np = g_numpos[b];
    long long Kl = 3LL * np;
    if (Kl > PP - 1) Kl = PP - 1;
    const int K = (int)Kl;
    if (K <= 0) {
        if (tid == 0) atomicAdd(&g_nsel, np);
        return;
    }
    const float* cl = g_closs + (size_t)b * PP;

    // Padding 0u (=0.0f) lands in bin 0; selection never descends there
    // (K-th largest closs > 0).
    unsigned int v[24];
    #pragma unroll
    for (int i = 0; i < 24; i++) {
        int idx = tid + i * 1024;
        v[i] = (idx < PP) ? __float_as_uint(cl[idx]) : 0u;
    }

    unsigned int prefix = 0, pmask = 0;
    int r = K;
    #pragma unroll
    for (int shift = 24; shift >= 0; shift -= 8) {
        if (tid < 256) hist[tid] = 0;
        __syncthreads();
        #pragma unroll
        for (int i = 0; i < 24; i++) {
            unsigned int u = v[i];
            bool act = ((u & pmask) == prefix);
            unsigned int bal = __ballot_sync(FULLMASK, act);
            if (act) {
                unsigned int bin = (u >> shift) & 255u;
                unsigned int peers = __match_any_sync(bal, bin);
                if (lane == __ffs(peers) - 1)
                    atomicAdd(&hist[bin], __popc(peers));
            }
        }
        __syncthreads();
        if (tid == 0) {
            int cum = 0; unsigned int sel = 0;
            for (int bin = 255; bin >= 0; bin--) {
                int nc = cum + hist[bin];
                if (nc >= r) { sel = (unsigned int)bin; break; }
                cum = nc;
            }
            s_sel = sel; s_r = r - cum;
        }
        __syncthreads();
        prefix |= s_sel << shift;
        pmask |= 0xFFu << shift;
        r = s_r;
    }
    const float theta = __uint_as_float(prefix);   // exact K-th largest

    if (tid == 0) { s_sum = 0.0; s_cnt = 0; }
    __syncthreads();
    double sum = 0.0; int cnt = 0;
    #pragma unroll
    for (int i = 0; i < 24; i++) {
        float f = __uint_as_float(v[i]);
        if (f > theta) { sum += (double)f; cnt++; }
    }
    #pragma unroll
    for (int o = 16; o; o >>= 1) {
        sum += __shfl_xor_sync(FULLMASK, sum, o);
        cnt += __shfl_xor_sync(FULLMASK, cnt, o);
    }
    if (lane == 0) { atomicAdd(&s_sum, sum); atomicAdd(&s_cnt, cnt); }
    __syncthreads();
    if (tid == 0) {
        double negsum = s_sum + (double)(K - s_cnt) * (double)theta;
        atomicAdd(&g_negcls, negsum);
        atomicAdd(&g_nsel, np + K);
    }
}

// ---------------------------------------------------------------------------
// Kernel 5: combine (non-selected rows each contribute exactly log C).
// ---------------------------------------------------------------------------
__global__ void k_final(float* out) {
    const int t = threadIdx.x;           // 64 threads
    int np = (t < BB) ? g_numpos[t] : 0;
    #pragma unroll
    for (int o = 16; o; o >>= 1) np += __shfl_xor_sync(FULLMASK, np, o);
    __shared__ int s_np[2];
    if ((t & 31) == 0) s_np[t >> 5] = np;
    __syncthreads();
    if (t == 0) {
        double N = (double)(s_np[0] + s_np[1]);
        double cls = g_poscls + g_negcls +
                     (double)((long long)BB * PP - (long long)g_nsel) * log((double)CC);
        out[0] = (float)(g_loc / N);
        out[1] = (float)(cls / N);
    }
}

// ---------------------------------------------------------------------------
// Launch
// ---------------------------------------------------------------------------
extern "C" void kernel_launch(void* const* d_in, const int* in_sizes, int n_in,
                              void* d_out, int out_size) {
    const float *loc = nullptr, *conf = nullptr, *tgt = nullptr, *anc = nullptr;
    for (int i = 0; i < n_in; i++) {
        long long s = in_sizes[i];
        if (s == (long long)BB * PP * 4)       loc  = (const float*)d_in[i];
        else if (s == (long long)BB * PP * CC) conf = (const float*)d_in[i];
        else if (s == (long long)BB * TT * 5)  tgt  = (const float*)d_in[i];
        else if (s == (long long)PP * 4)       anc  = (const float*)d_in[i];
    }
    float* out = (float*)d_out;

    k_init<<<(BB * TT + 255) / 256, 256>>>();

    dim3 g1((PP + 255) / 256, BB);
    k_matchA<<<g1, 256>>>(loc, tgt, anc);   // single IoU pass
    k_fix<<<BB, 32>>>(loc, tgt, anc);       // 1536-row scatter fixup

    // BB*PP = 1,572,096 rows = 49128 warps of 32 rows = 12282 blocks of 4 warps
    k_conf<<<(BB * PP) / (CW_WARPS * CW_ROWS), CW_WARPS * 32>>>(conf);

    k_select<<<BB, 1024>>>();

    k_final<<<1, 64>>>(out);
}

// round 10
// speedup vs baseline: 1.0170x; 1.0170x over previous
#include <cuda_runtime.h>
#include <math.h>

#define BB 64
#define PP 24564
#define CC 81
#define TT 24
#define THRESH_F 0.5f
#define FULLMASK 0xffffffffu

#define CW_WARPS 2                     // warps per k_conf block
#define CW_ROWS 32                     // rows per warp tile (one row per lane)
#define CW_F4 ((CW_ROWS * CC) / 4)     // 648 float4 per tile
#define CONF_TILES ((BB * PP) / CW_ROWS)   // 49128 warp tiles
#define CONF_BLOCKS 740                // 5 blocks/SM * 148
#define CONF_WSTRIDE (CONF_BLOCKS * CW_WARPS)

// ---------------------------------------------------------------------------
// Scratch (device globals — no allocation allowed)
// ---------------------------------------------------------------------------
__device__ unsigned long long g_bp[BB * TT];        // packed (iou_bits<<32)|~p
__device__ unsigned char g_lbl[(size_t)BB * PP];    // 0 = negative, else class label
__device__ unsigned char g_match[(size_t)BB * PP];  // 0xFF = bestov<=0.5, else bt
__device__ float g_closs[(size_t)BB * PP];          // per (b,p) neg conf loss
__device__ double g_loc, g_poscls, g_negcls;
__device__ int g_numpos[BB];
__device__ int g_nsel;

__device__ __forceinline__ void cp_async16(unsigned int smem_dst, const void* gsrc) {
    asm volatile("cp.async.cg.shared.global [%0], [%1], 16;"
                 :: "r"(smem_dst), "l"(gsrc));
}

// ---------------------------------------------------------------------------
// Kernel 0: zero-init scratch
// ---------------------------------------------------------------------------
__global__ void k_init() {
    int i = blockIdx.x * blockDim.x + threadIdx.x;
    if (i < BB * TT) g_bp[i] = 0ULL;
    if (i < BB) g_numpos[i] = 0;
    if (i == 0) { g_loc = 0.0; g_poscls = 0.0; g_negcls = 0.0; g_nsel = 0; }
}

// ---------------------------------------------------------------------------
// Kernel 1 (merged): ONE IoU pass does both jobs.
//  - per-prior best truth (sequential register argmax, first-index ties)
//  - per-truth best prior (smem u64 atomicMax behind __any_sync early-out)
//  - best>0.5 rows: label + smooth-L1 loc loss + num_pos, g_match=bt
//  - best<=0.5 rows: g_match=0xFF (k_fix may flip them via scatter)
// ---------------------------------------------------------------------------
__global__ void __launch_bounds__(256) k_matchA(const float* __restrict__ loc_pred,
                                                const float* __restrict__ targets,
                                                const float* __restrict__ anchors) {
    __shared__ float4 s_box[TT];      // xyxy
    __shared__ float  s_ta[TT];       // truth area
    __shared__ float4 s_cwh[TT];      // cx,cy,w,h
    __shared__ float  s_lblv[TT];
    __shared__ unsigned long long s_best[TT];
    __shared__ double s_loc;
    __shared__ int s_np;

    const int b = blockIdx.y;
    const int tid = threadIdx.x;
    if (tid == 0) { s_loc = 0.0; s_np = 0; }
    if (tid < TT) {
        const float* tr = targets + ((size_t)b * TT + tid) * 5;
        float x0 = tr[0], y0 = tr[1], x1 = tr[2], y1 = tr[3];
        s_box[tid] = make_float4(x0, y0, x1, y1);
        s_ta[tid] = (x1 - x0) * (y1 - y0);
        s_cwh[tid] = make_float4((x0 + x1) * 0.5f, (y0 + y1) * 0.5f, x1 - x0, y1 - y0);
        s_lblv[tid] = tr[4];
        s_best[tid] = 0ULL;
    }
    __syncthreads();

    const int p = blockIdx.x * blockDim.x + tid;
    const bool valid = (p < PP);
    float4 a = make_float4(0.f, 0.f, 1.f, 1.f);
    if (valid) a = ((const float4*)anchors)[p];
    const float ax0 = a.x - a.z * 0.5f, ay0 = a.y - a.w * 0.5f;
    const float ax1 = a.x + a.z * 0.5f, ay1 = a.y + a.w * 0.5f;
    const float aarea = (ax1 - ax0) * (ay1 - ay0);

    float best = -1.0f; int bt = 0;
    #pragma unroll
    for (int t = 0; t < TT; t++) {
        float4 tb = s_box[t];
        float lx = fmaxf(tb.x, ax0), ly = fmaxf(tb.y, ay0);
        float rx = fminf(tb.z, ax1), ry = fminf(tb.w, ay1);
        float w = fmaxf(rx - lx, 0.f), h = fmaxf(ry - ly, 0.f);
        float inter = w * h;
        float iou = __fdividef(inter, s_ta[t] + aarea - inter);
        if (iou > best) { best = iou; bt = t; }       // strict >: first index wins

        unsigned long long pk = 0ULL;
        if (valid)
            pk = ((unsigned long long)__float_as_uint(iou) << 32)
                 | (unsigned long long)(unsigned int)(~p);
        // Early-out: s_best[t] monotonic; a stale read only skips the skip.
        unsigned long long cur = s_best[t];
        if (__any_sync(FULLMASK, pk > cur)) {
            #pragma unroll
            for (int o = 16; o; o >>= 1) {
                unsigned long long oth = __shfl_down_sync(FULLMASK, pk, o);
                if (oth > pk) pk = oth;
            }
            if ((tid & 31) == 0) atomicMax(&s_best[t], pk);
        }
    }

    if (valid) {
        const size_t row = (size_t)b * PP + p;
        unsigned char lbl = 0, mb = 0xFF;
        if (best > THRESH_F) {
            mb = (unsigned char)bt;
            lbl = (unsigned char)(int)s_lblv[bt];
            float4 lp = ((const float4*)loc_pred)[row];
            float4 c = s_cwh[bt];
            float e0 = (c.x - a.x) / a.z;
            float e1 = (c.y - a.y) / a.w;
            float e2 = __logf(c.z) - __logf(a.z);
            float e3 = __logf(c.w) - __logf(a.w);
            float d, ad, lt = 0.f;
            d = lp.x - e0; ad = fabsf(d); lt += (ad < 1.f) ? 0.5f * d * d : ad - 0.5f;
            d = lp.y - e1; ad = fabsf(d); lt += (ad < 1.f) ? 0.5f * d * d : ad - 0.5f;
            d = lp.z - e2; ad = fabsf(d); lt += (ad < 1.f) ? 0.5f * d * d : ad - 0.5f;
            d = lp.w - e3; ad = fabsf(d); lt += (ad < 1.f) ? 0.5f * d * d : ad - 0.5f;
            atomicAdd(&s_loc, (double)lt);
            atomicAdd(&s_np, 1);
        }
        g_lbl[row] = lbl;
        g_match[row] = mb;
    }
    __syncthreads();
    if (tid < TT) atomicMax(&g_bp[b * TT + tid], s_best[tid]);
    if (tid == 0 && s_np) {
        atomicAdd(&g_loc, s_loc);
        atomicAdd(&g_numpos[b], s_np);
    }
}

// ---------------------------------------------------------------------------
// Kernel 2: scatter fixup — 64 blocks x 32 threads, 1536 candidate rows.
// Row p = best_prior[b][t] becomes positive with truth t (last t wins among
// duplicates) iff its best overlap was <= 0.5 (g_match == 0xFF).
// ---------------------------------------------------------------------------
__global__ void k_fix(const float* __restrict__ loc_pred,
                      const float* __restrict__ targets,
                      const float* __restrict__ anchors) {
    const int b = blockIdx.x;
    const int t = threadIdx.x;
    if (t >= TT) return;
    unsigned long long pk = g_bp[b * TT + t];
    const int p = (int)(~(unsigned int)(pk & 0xFFFFFFFFull));
    unsigned int peers = __match_any_sync(0x00FFFFFFu, p);
    if (t != 31 - __clz(peers)) return;          // last t wins
    const size_t row = (size_t)b * PP + p;
    if (g_match[row] != 0xFF) return;            // bt-match already positive

    const float* tr = targets + ((size_t)b * TT + t) * 5;
    float x0 = tr[0], y0 = tr[1], x1 = tr[2], y1 = tr[3];
    g_lbl[row] = (unsigned char)(int)tr[4];

    float4 a = ((const float4*)anchors)[p];
    float4 lp = ((const float4*)loc_pred)[row];
    float e0 = ((x0 + x1) * 0.5f - a.x) / a.z;
    float e1 = ((y0 + y1) * 0.5f - a.y) / a.w;
    float e2 = __logf(x1 - x0) - __logf(a.z);
    float e3 = __logf(y1 - y0) - __logf(a.w);
    float d, ad, lt = 0.f;
    d = lp.x - e0; ad = fabsf(d); lt += (ad < 1.f) ? 0.5f * d * d : ad - 0.5f;
    d = lp.y - e1; ad = fabsf(d); lt += (ad < 1.f) ? 0.5f * d * d : ad - 0.5f;
    d = lp.z - e2; ad = fabsf(d); lt += (ad < 1.f) ? 0.5f * d * d : ad - 0.5f;
    d = lp.w - e3; ad = fabsf(d); lt += (ad < 1.f) ? 0.5f * d * d : ad - 0.5f;
    atomicAdd(&g_loc, (double)lt);
    atomicAdd(&g_numpos[b], 1);
}

// ---------------------------------------------------------------------------
// Kernel 3: the 509 MB streaming pass — cp.async double-buffered pipeline.
// Each warp loops over ~33 tiles of 32 rows (10.4 KB): prefetch tile n+1 via
// cp.async.cg into buffer B while computing tile n from buffer A. Loads stay
// outstanding through the whole compute phase -> DRAM latency hidden.
// Thread-per-row compute: 81 conflict-free LDS (stride 81 -> bank 17*lane+e
// mod 32) + 81 __expf, no shuffles, no predicates.
// ---------------------------------------------------------------------------
__global__ void __launch_bounds__(CW_WARPS * 32) k_conf(const float* __restrict__ conf_pred) {
    __shared__ float s[CW_WARPS][2][CW_ROWS * CC];    // 2 x 2 x 10368 B = 41.5 KB

    const int lane = threadIdx.x & 31;
    const int w = threadIdx.x >> 5;
    const int gw = blockIdx.x * CW_WARPS + w;          // global warp id

    unsigned int sbase[2];
    sbase[0] = (unsigned int)__cvta_generic_to_shared(&s[w][0][0]);
    sbase[1] = (unsigned int)__cvta_generic_to_shared(&s[w][1][0]);

    int tile = gw;
    if (tile >= CONF_TILES) return;

    // prefetch first tile into buf 0
    {
        const float4* src = (const float4*)(conf_pred + (size_t)tile * (CW_ROWS * CC));
        for (int i = lane; i < CW_F4; i += 32)
            cp_async16(sbase[0] + i * 16, src + i);
        asm volatile("cp.async.commit_group;");
    }

    int buf = 0;
    for (; tile < CONF_TILES; tile += CONF_WSTRIDE) {
        // prefetch next tile into the other buffer (commit even when empty)
        const int nt = tile + CONF_WSTRIDE;
        if (nt < CONF_TILES) {
            const float4* src = (const float4*)(conf_pred + (size_t)nt * (CW_ROWS * CC));
            for (int i = lane; i < CW_F4; i += 32)
                cp_async16(sbase[buf ^ 1] + i * 16, src + i);
        }
        asm volatile("cp.async.commit_group;");
        asm volatile("cp.async.wait_group 1;");   // current buffer complete
        __syncwarp();

        // one lane = one row
        const float* rp = s[w][buf] + lane * CC;
        float a0 = 0.f, a1 = 0.f, a2 = 0.f;
        #pragma unroll 9
        for (int e = 0; e < CC; e += 3) {
            a0 += __expf(rp[e]);
            a1 += __expf(rp[e + 1]);
            a2 += __expf(rp[e + 2]);
        }
        const float lse = __logf((a0 + a1) + a2);

        const size_t row = (size_t)tile * CW_ROWS + lane;
        const int lbl = g_lbl[row];             // coalesced byte load
        float closs = 0.f;
        if (lbl == 0) {
            closs = lse - rp[0];                // candidate negative
        } else {                                // positive (rare)
            atomicAdd(&g_poscls, (double)(lse - rp[lbl]));
        }
        g_closs[row] = closs;                   // coalesced store

        buf ^= 1;
        __syncwarp();                           // all lanes done before overwrite
    }
}

// ---------------------------------------------------------------------------
// Kernel 4: per-batch exact K-th-largest; register-cached values, warp-
// aggregated histogram atomics (closs clusters into few bins).
// ---------------------------------------------------------------------------
__global__ void __launch_bounds__(1024) k_select() {
    __shared__ int hist[256];
    __shared__ unsigned int s_sel;
    __shared__ int s_r;
    __shared__ double s_sum;
    __shared__ int s_cnt;

    const int b = blockIdx.x;
    const int tid = threadIdx.x;
    const int lane = tid & 31;
    const int np = g_numpos[b];
    long long Kl = 3LL * np;
    if (Kl > PP - 1) Kl = PP - 1;
    const int K = (int)Kl;
    if (K <= 0) {
        if (tid == 0) atomicAdd(&g_nsel, np);
        return;
    }
    const float* cl = g_closs + (size_t)b * PP;

    // Padding 0u (=0.0f) lands in bin 0; selection never descends there
    // (K-th largest closs > 0).
    unsigned int v[24];
    #pragma unroll
    for (int i = 0; i < 24; i++) {
        int idx = tid + i * 1024;
        v[i] = (idx < PP) ? __float_as_uint(cl[idx]) : 0u;
    }

    unsigned int prefix = 0, pmask = 0;
    int r = K;
    #pragma unroll
    for (int shift = 24; shift >= 0; shift -= 8) {
        if (tid < 256) hist[tid] = 0;
        __syncthreads();
        #pragma unroll
        for (int i = 0; i < 24; i++) {
            unsigned int u = v[i];
            bool act = ((u & pmask) == prefix);
            unsigned int bal = __ballot_sync(FULLMASK, act);
            if (act) {
                unsigned int bin = (u >> shift) & 255u;
                unsigned int peers = __match_any_sync(bal, bin);
                if (lane == __ffs(peers) - 1)
                    atomicAdd(&hist[bin], __popc(peers));
            }
        }
        __syncthreads();
        if (tid == 0) {
            int cum = 0; unsigned int sel = 0;
            for (int bin = 255; bin >= 0; bin--) {
                int nc = cum + hist[bin];
                if (nc >= r) { sel = (unsigned int)bin; break; }
                cum = nc;
            }
            s_sel = sel; s_r = r - cum;
        }
        __syncthreads();
        prefix |= s_sel << shift;
        pmask |= 0xFFu << shift;
        r = s_r;
    }
    const float theta = __uint_as_float(prefix);   // exact K-th largest

    if (tid == 0) { s_sum = 0.0; s_cnt = 0; }
    __syncthreads();
    double sum = 0.0; int cnt = 0;
    #pragma unroll
    for (int i = 0; i < 24; i++) {
        float f = __uint_as_float(v[i]);
        if (f > theta) { sum += (double)f; cnt++; }
    }
    #pragma unroll
    for (int o = 16; o; o >>= 1) {
        sum += __shfl_xor_sync(FULLMASK, sum, o);
        cnt += __shfl_xor_sync(FULLMASK, cnt, o);
    }
    if (lane == 0) { atomicAdd(&s_sum, sum); atomicAdd(&s_cnt, cnt); }
    __syncthreads();
    if (tid == 0) {
        double negsum = s_sum + (double)(K - s_cnt) * (double)theta;
        atomicAdd(&g_negcls, negsum);
        atomicAdd(&g_nsel, np + K);
    }
}

// ---------------------------------------------------------------------------
// Kernel 5: combine (non-selected rows each contribute exactly log C).
// ---------------------------------------------------------------------------
__global__ void k_final(float* out) {
    const int t = threadIdx.x;           // 64 threads
    int np = (t < BB) ? g_numpos[t] : 0;
    #pragma unroll
    for (int o = 16; o; o >>= 1) np += __shfl_xor_sync(FULLMASK, np, o);
    __shared__ int s_np[2];
    if ((t & 31) == 0) s_np[t >> 5] = np;
    __syncthreads();
    if (t == 0) {
        double N = (double)(s_np[0] + s_np[1]);
        double cls = g_poscls + g_negcls +
                     (double)((long long)BB * PP - (long long)g_nsel) * log((double)CC);
        out[0] = (float)(g_loc / N);
        out[1] = (float)(cls / N);
    }
}

// ---------------------------------------------------------------------------
// Launch
// ---------------------------------------------------------------------------
extern "C" void kernel_launch(void* const* d_in, const int* in_sizes, int n_in,
                              void* d_out, int out_size) {
    const float *loc = nullptr, *conf = nullptr, *tgt = nullptr, *anc = nullptr;
    for (int i = 0; i < n_in; i++) {
        long long s = in_sizes[i];
        if (s == (long long)BB * PP * 4)       loc  = (const float*)d_in[i];
        else if (s == (long long)BB * PP * CC) conf = (const float*)d_in[i];
        else if (s == (long long)BB * TT * 5)  tgt  = (const float*)d_in[i];
        else if (s == (long long)PP * 4)       anc  = (const float*)d_in[i];
    }
    float* out = (float*)d_out;

    k_init<<<(BB * TT + 255) / 256, 256>>>();

    dim3 g1((PP + 255) / 256, BB);
    k_matchA<<<g1, 256>>>(loc, tgt, anc);   // single IoU pass
    k_fix<<<BB, 32>>>(loc, tgt, anc);       // 1536-row scatter fixup

    k_conf<<<CONF_BLOCKS, CW_WARPS * 32>>>(conf);

    k_select<<<BB, 1024>>>();

    k_final<<<1, 64>>>(out);
}